// round 14
// baseline (speedup 1.0000x reference)
#include <cuda_runtime.h>
#include <cuda_fp16.h>
#include <cstdint>
#include <math.h>

#define T_     256
#define B_     32
#define VOCAB_ 32000
#define EMB_   512
#define HID_   1024
#define G_     4096   // 4*HID
#define TB_    8192   // T_*B_
#define NBLK   128    // persistent blocks (1 per SM)
#define UPB    8      // hidden units per block (128*8 = 1024)
#define BH     (B_ * HID_)
#define NW     8      // warps per block in lstm_persist
#define NCTR   8      // distributed barrier counters (16 blocks each)

// fp16 recurrence chunking: 32 m x 32 k halves per chunk, stride 40 halves
#define CSTH   40
#define CBH    (32 * CSTH * 2)        // 2560 B per chunk buffer

// fp16 pipelined GEMM: 128x128 tile, 4 warps (64x64), K-stage 32, 3 stages,
// 2 blocks/SM co-resident.
#define GBM 128
#define GBN 128
#define GBK 32
#define GSTH 40                        // smem row stride (halves)
#define A_STAGE_H (GBM * GSTH)         // 5120 halves
#define B_STAGE_H (GBN * GSTH)         // 5120 halves
#define STAGE_H (A_STAGE_H + B_STAGE_H)
#define GEMM_SMEM (3 * STAGE_H * 2)    // 61440 B
#define GSW 8                          // supertile width (N tiles)

// ---------------- scratch (device globals; no allocations allowed) ----------
__device__ float g_X0[TB_ * EMB_];         // used as half[TB][EMB]
__device__ float g_HA[TB_ * HID_];         // used as half[TB][HID]
__device__ float g_HB[TB_ * HID_];         // used as half[TB][HID]
__device__ float g_Xg[(size_t)TB_ * G_];   // f32 gate priors; later WdT half
__device__ float g_Wr[HID_ * G_];          // transposed half pre-gate weights
__device__ float g_h[2 * BH];              // used as half[2][BH]
__device__ unsigned g_bar[NCTR * 32];      // 8 counters, 128 B apart

// ---------------- helpers ---------------------------------------------------
__device__ __forceinline__ void mma_fp16(float* d, const uint32_t* a, const uint32_t* b) {
    asm volatile(
        "mma.sync.aligned.m16n8k16.row.col.f32.f16.f16.f32 "
        "{%0,%1,%2,%3}, {%4,%5,%6,%7}, {%8,%9}, {%0,%1,%2,%3};\n"
        : "+f"(d[0]), "+f"(d[1]), "+f"(d[2]), "+f"(d[3])
        : "r"(a[0]), "r"(a[1]), "r"(a[2]), "r"(a[3]), "r"(b[0]), "r"(b[1]));
}

__device__ __forceinline__ float sigm(float x) { return 1.f / (1.f + expf(-x)); }

__device__ __forceinline__ unsigned ld_acq(const unsigned* p) {
    unsigned v;
    asm volatile("ld.acquire.gpu.u32 %0, [%1];" : "=r"(v) : "l"(p) : "memory");
    return v;
}

__device__ __forceinline__ void cp16(uint32_t dst, const void* src) {
    asm volatile("cp.async.cg.shared.global [%0], [%1], 16;" :: "r"(dst), "l"(src));
}
#define CP_COMMIT() asm volatile("cp.async.commit_group;")
#define CP_WAIT(N)  asm volatile("cp.async.wait_group %0;" :: "n"(N))

__device__ __forceinline__ uint32_t pack_half2(float a, float b) {
    __half2 h = __floats2half2_rn(a, b);
    return *reinterpret_cast<uint32_t*>(&h);
}

// ---------------- embedding gather (-> half) --------------------------------
__global__ void gather_kernel(const int* __restrict__ data,
                              const float* __restrict__ emb,
                              __half* __restrict__ X0h) {
    int tb = blockIdx.x;
    int idx = data[tb];
    const float4* src = reinterpret_cast<const float4*>(emb + (size_t)idx * EMB_);
    float4 v = src[threadIdx.x];
    uint2 pk = make_uint2(pack_half2(v.x, v.y), pack_half2(v.z, v.w));
    reinterpret_cast<uint2*>(X0h + (size_t)tb * EMB_)[threadIdx.x] = pk;
}

// ---------------- transpose + f32->half: out[n][k] = half(in[k][n]) ---------
__global__ void trans_half(const float* __restrict__ in, __half* __restrict__ outp,
                           int Kdim, int Ndim) {
    __shared__ float t[32][33];
    int nb = blockIdx.x * 32, kb = blockIdx.y * 32;
    int x = threadIdx.x, y = threadIdx.y;   // block (32, 8)
#pragma unroll
    for (int i = 0; i < 32; i += 8)
        t[y + i][x] = in[(size_t)(kb + y + i) * Ndim + nb + x];
    __syncthreads();
#pragma unroll
    for (int i = 0; i < 32; i += 8)
        outp[(size_t)(nb + y + i) * Kdim + kb + x] = __float2half(t[x][y + i]);
}

// ---------------- state zero + barrier reset --------------------------------
__global__ void zero_state(float* __restrict__ h, unsigned* __restrict__ bar) {
    int i = blockIdx.x * blockDim.x + threadIdx.x;
    if (i < 2 * BH) h[i] = 0.f;
    if (i < NCTR * 32) bar[i] = 0u;
}

// ---------------- fp16 pipelined GEMM: C = A @ Bt^T + bias ------------------
// A [M, lda] half row-major, Bt [N, K] half row-major (pre-transposed).
// 128x128 tile, 128 threads (4 warps, 64x64 warp tiles), 3-stage cp.async
// pipeline (K-stage 32), 2 blocks/SM, supertile swizzle. C f32.
__global__ __launch_bounds__(128, 2) void gemm_fp16_pipe(
    const __half* __restrict__ A, int lda,
    const __half* __restrict__ Bt,
    const float* __restrict__ bias,
    float* __restrict__ C, int ldc, int K, int ntiles, int mtiles)
{
    extern __shared__ char smc[];

    int lin = blockIdx.x;
    int n_t, m_t;
    {
        int full = ntiles / GSW;
        int blocksFull = full * GSW * mtiles;
        if (lin < blocksFull) {
            int sid = lin / (GSW * mtiles);
            int r = lin - sid * (GSW * mtiles);
            n_t = sid * GSW + (r % GSW);
            m_t = r / GSW;
        } else {
            int r = lin - blocksFull;
            int wd = ntiles - full * GSW;
            n_t = full * GSW + (r % wd);
            m_t = r / wd;
        }
    }
    const int n0 = n_t * GBN;
    const int m0 = m_t * GBM;

    const int tid = threadIdx.x;
    const int lane = tid & 31, warp = tid >> 5;
    const int wm = (warp & 1) * 64;       // 2 M groups
    const int wn = (warp >> 1) * 64;      // 2 N groups
    const int g = lane >> 2, tig = lane & 3;

    const uint32_t sm_u32 = (uint32_t)__cvta_generic_to_shared(smc);

    float acc[4][8][4];
#pragma unroll
    for (int i = 0; i < 4; i++)
#pragma unroll
        for (int j = 0; j < 8; j++)
#pragma unroll
            for (int r = 0; r < 4; r++) acc[i][j][r] = 0.f;

    auto issue_stage = [&](int kb, int s) {
        int k0 = kb * GBK;
        uint32_t aS = sm_u32 + (uint32_t)(s * STAGE_H) * 2;
        uint32_t bS = aS + A_STAGE_H * 2;
#pragma unroll
        for (int i = 0; i < 4; i++) {               // A: 128 rows x 32 halves
            int idx = tid + i * 128;
            int row = idx >> 2, q = idx & 3;
            cp16(aS + (uint32_t)(row * GSTH + q * 8) * 2,
                 A + (size_t)(m0 + row) * lda + k0 + q * 8);
        }
#pragma unroll
        for (int i = 0; i < 4; i++) {               // B: 128 rows x 32 halves
            int idx = tid + i * 128;
            int row = idx >> 2, q = idx & 3;
            cp16(bS + (uint32_t)(row * GSTH + q * 8) * 2,
                 Bt + (size_t)(n0 + row) * K + k0 + q * 8);
        }
        CP_COMMIT();
    };
    auto compute_stage = [&](int s) {
        const __half* aS = reinterpret_cast<const __half*>(smc) + s * STAGE_H;
        const __half* bS = aS + A_STAGE_H;
#pragma unroll
        for (int it = 0; it < 2; it++) {
            const int ks = it * 16;
            uint32_t af[4][4];
#pragma unroll
            for (int mt = 0; mt < 4; mt++) {
                int mb = wm + mt * 16 + g;
                af[mt][0] = *reinterpret_cast<const uint32_t*>(aS + mb * GSTH + ks + 2 * tig);
                af[mt][1] = *reinterpret_cast<const uint32_t*>(aS + (mb + 8) * GSTH + ks + 2 * tig);
                af[mt][2] = *reinterpret_cast<const uint32_t*>(aS + mb * GSTH + ks + 2 * tig + 8);
                af[mt][3] = *reinterpret_cast<const uint32_t*>(aS + (mb + 8) * GSTH + ks + 2 * tig + 8);
            }
#pragma unroll
            for (int nt = 0; nt < 8; nt++) {
                int nb = wn + nt * 8 + g;
                uint32_t bf[2];
                bf[0] = *reinterpret_cast<const uint32_t*>(bS + nb * GSTH + ks + 2 * tig);
                bf[1] = *reinterpret_cast<const uint32_t*>(bS + nb * GSTH + ks + 2 * tig + 8);
#pragma unroll
                for (int mt = 0; mt < 4; mt++)
                    mma_fp16(acc[mt][nt], af[mt], bf);
            }
        }
    };

    const int nk = K >> 5;
    issue_stage(0, 0);
    issue_stage(1, 1);
    int s = 0;
    for (int kb = 0; kb < nk; kb++) {
        if (kb < nk - 1) { CP_WAIT(1); } else { CP_WAIT(0); }
        __syncthreads();
        compute_stage(s);
        if (kb + 2 < nk) {
            int nb = s + 2; if (nb >= 3) nb -= 3;
            issue_stage(kb + 2, nb);
        }
        s = s + 1; if (s == 3) s = 0;
    }

#pragma unroll
    for (int mt = 0; mt < 4; mt++) {
        int m = m0 + wm + mt * 16 + g;
#pragma unroll
        for (int nt = 0; nt < 8; nt++) {
            int n = n0 + wn + nt * 8 + 2 * tig;
            float bx = bias[n], by = bias[n + 1];
            float2 v0 = make_float2(acc[mt][nt][0] + bx, acc[mt][nt][1] + by);
            float2 v1 = make_float2(acc[mt][nt][2] + bx, acc[mt][nt][3] + by);
            *reinterpret_cast<float2*>(C + (size_t)m * ldc + n) = v0;
            *reinterpret_cast<float2*>(C + (size_t)(m + 8) * ldc + n) = v1;
        }
    }
}

// ---------------- persistent LSTM layer: fp16 mma, distributed barrier ------
#define WHS_BYTES 65536
#define HB_BYTES  (NW * 2 * CBH)       // 40960
#define SMEM_PERSIST (WHS_BYTES + HB_BYTES)

__global__ __launch_bounds__(256, 1) void lstm_persist(
    const float* __restrict__ Xg,
    const float* __restrict__ Wh,      // f32 [HID_][G_] (rows Din..Din+H of W)
    __half* __restrict__ hbuf,         // half [2][BH] (zeroed)
    __half* __restrict__ Hout,         // half for next layer's fp16 GEMM
    unsigned* __restrict__ bar)        // [NCTR*32] distributed counters
{
    extern __shared__ char smx[];
    uint2* Whs = reinterpret_cast<uint2*>(smx);          // [64 ko][4 nt][32 lane]
    float* scr = reinterpret_cast<float*>(smx + WHS_BYTES);  // alias of chunk bufs

    const int tid = threadIdx.x;
    const int lane = tid & 31, warp = tid >> 5;
    const int g = lane >> 2, tig = lane & 3;
    const int u0 = blockIdx.x * UPB;

    const uint32_t smem_u32 = (uint32_t)__cvta_generic_to_shared(smx);
    const uint32_t hb_u32 = smem_u32 + WHS_BYTES + warp * 2 * CBH;
    const uint32_t* hb_gen =
        reinterpret_cast<const uint32_t*>(smx + WHS_BYTES + warp * 2 * CBH);

    // ---- one-time: Wh slice -> half B-fragments (m16n8k16) ----
    for (int ko = warp; ko < 64; ko += NW) {
        int k0 = ko * 16;
#pragma unroll
        for (int nt = 0; nt < 4; nt++) {
            int col = nt * HID_ + u0 + g;
            uint32_t r0 = pack_half2(Wh[(size_t)(k0 + 2 * tig) * G_ + col],
                                     Wh[(size_t)(k0 + 2 * tig + 1) * G_ + col]);
            uint32_t r1 = pack_half2(Wh[(size_t)(k0 + 2 * tig + 8) * G_ + col],
                                     Wh[(size_t)(k0 + 2 * tig + 9) * G_ + col]);
            Whs[(ko * 4 + nt) * 32 + lane] = make_uint2(r0, r1);
        }
    }
    __syncthreads();

    // pointwise mapping (identical output layout to previous rounds)
    const int pm = tid >> 3, pul = tid & 7;
    const int pmt = pm >> 4;
    const int pgg = (pm & 15) & 7, phi = (pm & 15) >> 3;
    const int pr = phi * 2 + (pul & 1);
    const int pln = pgg * 4 + (pul >> 1);
    const size_t xgbase = (size_t)pm * G_ + u0 + pul;

    const int kw = warp * 128;         // this warp's K base (halves)

    float creg = 0.f;
    float xr[4];
#pragma unroll
    for (int s = 0; s < 4; s++) xr[s] = Xg[xgbase + s * HID_];

    for (int t = 0; t < T_; t++) {
        const __half* hin = hbuf + (t & 1) * BH;
        __half* hnx = hbuf + ((t + 1) & 1) * BH;

        float acc[2][4][4];
#pragma unroll
        for (int mt = 0; mt < 2; mt++)
#pragma unroll
            for (int nt = 0; nt < 4; nt++)
#pragma unroll
                for (int r = 0; r < 4; r++) acc[mt][nt][r] = 0.f;

        // chunk = 32 m x 32 k halves; 128 cp16 per chunk, 4 per lane
        auto cp_chunk = [&](int c, int b) {
            const int kbase = kw + c * 32;
            const uint32_t dbase = hb_u32 + b * CBH;
#pragma unroll
            for (int i = 0; i < 4; i++) {
                int idx = i * 32 + lane;
                int row = idx >> 2, q = idx & 3;
                cp16(dbase + (uint32_t)(row * (CSTH * 2) + q * 16),
                     hin + (size_t)row * HID_ + kbase + q * 8);
            }
            CP_COMMIT();
        };
        auto compute_chunk = [&](int c, int b) {
            const uint32_t* buf = hb_gen + b * (CBH / 4);
#pragma unroll
            for (int ks16 = 0; ks16 < 2; ks16++) {
                int ko = warp * 8 + c * 2 + ks16;
                uint32_t af[2][4];
#pragma unroll
                for (int mt = 0; mt < 2; mt++) {
                    int mb = mt * 16;
                    int base0 = (mb + g) * (CSTH / 2) + ks16 * 8 + tig;
                    int base1 = (mb + g + 8) * (CSTH / 2) + ks16 * 8 + tig;
                    af[mt][0] = buf[base0];
                    af[mt][1] = buf[base1];
                    af[mt][2] = buf[base0 + 4];
                    af[mt][3] = buf[base1 + 4];
                }
#pragma unroll
                for (int nt = 0; nt < 4; nt++) {
                    uint2 bb = Whs[(ko * 4 + nt) * 32 + lane];
                    uint32_t bf[2] = {bb.x, bb.y};
                    mma_fp16(acc[0][nt], af[0], bf);
                    mma_fp16(acc[1][nt], af[1], bf);
                }
            }
        };

        cp_chunk(0, 0);
        cp_chunk(1, 1);
        CP_WAIT(1); __syncwarp();
        compute_chunk(0, 0);
        cp_chunk(2, 0);
        CP_WAIT(1); __syncwarp();
        compute_chunk(1, 1);
        cp_chunk(3, 1);
        CP_WAIT(1); __syncwarp();
        compute_chunk(2, 0);
        CP_WAIT(0); __syncwarp();
        compute_chunk(3, 1);

        // ---- reduce K-partials across 8 warps (scr aliases chunk bufs) ----
        __syncthreads();
#pragma unroll
        for (int mt = 0; mt < 2; mt++)
#pragma unroll
            for (int nt = 0; nt < 4; nt++)
#pragma unroll
                for (int r = 0; r < 4; r++) {
                    int ridx = mt * 16 + nt * 4 + r;
                    scr[((warp * 32 + ridx) << 5) + lane] = acc[mt][nt][r];
                }
        __syncthreads();

        // ---- pointwise: one (batch, unit) pair per thread ----
        float hh;
        {
            float gv[4];
#pragma unroll
            for (int s = 0; s < 4; s++) {
                int ridx = pmt * 16 + s * 4 + pr;
                float v = 0.f;
#pragma unroll
                for (int w = 0; w < NW; w++)
                    v += scr[((w * 32 + ridx) << 5) + pln];
                gv[s] = v + xr[s];
            }
            float cc = creg;
            cc = sigm(gv[2] + 1.f) * cc + sigm(gv[0]) * tanhf(gv[1]);
            hh = sigm(gv[3]) * tanhf(cc);
            creg = cc;
            hnx[pm * HID_ + u0 + pul] = __float2half(hh);
        }

        // ---- distributed barrier: 8 counters x 16 arrivals ----
        if (t < T_ - 1) {
            __syncthreads();           // all hnx stores issued
            if (tid == 0) {
                __threadfence();
                atomicAdd(&bar[(blockIdx.x & (NCTR - 1)) << 5], 1u);
            }
            // overlap latency of arrival propagation
            Hout[((size_t)(t * B_ + pm)) * HID_ + u0 + pul] = __float2half(hh);
            const size_t xb = xgbase + (size_t)(t + 1) * B_ * G_;
#pragma unroll
            for (int s = 0; s < 4; s++) xr[s] = Xg[xb + s * HID_];
            if (warp == 0 && lane < NCTR) {
                const unsigned target = (unsigned)(t + 1) * (NBLK / NCTR);
                while (ld_acq(&bar[lane << 5]) < target) { }
            }
            __syncthreads();
        } else {
            Hout[((size_t)(t * B_ + pm)) * HID_ + u0 + pul] = __float2half(hh);
        }
    }
}

// ---------------- launch ----------------------------------------------------
extern "C" void kernel_launch(void* const* d_in, const int* in_sizes, int n_in,
                              void* d_out, int out_size) {
    const int*   data = (const int*)d_in[0];
    const float* emb  = (const float*)d_in[2];
    const float* W0   = (const float*)d_in[3];
    const float* b0   = (const float*)d_in[4];
    const float* W1   = (const float*)d_in[5];
    const float* b1   = (const float*)d_in[6];
    const float* W2   = (const float*)d_in[7];
    const float* b2   = (const float*)d_in[8];
    const float* Wd   = (const float*)d_in[9];
    const float* bd   = (const float*)d_in[10];
    float* out = (float*)d_out;
    (void)in_sizes; (void)n_in; (void)out_size;

    float *X0, *HA, *HB, *Xg, *Wr, *h;
    unsigned* bar;
    cudaGetSymbolAddress((void**)&X0, g_X0);
    cudaGetSymbolAddress((void**)&HA, g_HA);
    cudaGetSymbolAddress((void**)&HB, g_HB);
    cudaGetSymbolAddress((void**)&Xg, g_Xg);
    cudaGetSymbolAddress((void**)&Wr, g_Wr);
    cudaGetSymbolAddress((void**)&h,  g_h);
    cudaGetSymbolAddress((void**)&bar, g_bar);

    __half* X0h = reinterpret_cast<__half*>(X0);
    __half* HAh = reinterpret_cast<__half*>(HA);
    __half* HBh = reinterpret_cast<__half*>(HB);
    __half* Wrh = reinterpret_cast<__half*>(Wr);
    __half* WdTh = reinterpret_cast<__half*>(Xg);
    __half* hh_ = reinterpret_cast<__half*>(h);

    cudaFuncSetAttribute(lstm_persist, cudaFuncAttributeMaxDynamicSharedMemorySize,
                         SMEM_PERSIST);
    cudaFuncSetAttribute(gemm_fp16_pipe, cudaFuncAttributeMaxDynamicSharedMemorySize,
                         GEMM_SMEM);

    gather_kernel<<<TB_, 128>>>(data, emb, X0h);

    const int zgrid = (2 * BH + 255) / 256;
    const int MT = TB_ / GBM;          // 64

    // layer 0 (Din = 512)
    trans_half<<<dim3(G_ / 32, EMB_ / 32), dim3(32, 8)>>>(W0, Wrh, EMB_, G_);
    zero_state<<<zgrid, 256>>>(h, bar);
    gemm_fp16_pipe<<<MT * (G_ / GBN), 128, GEMM_SMEM>>>(
        X0h, EMB_, Wrh, b0, Xg, G_, EMB_, G_ / GBN, MT);
    lstm_persist<<<NBLK, 256, SMEM_PERSIST>>>(Xg, W0 + (size_t)EMB_ * G_, hh_, HAh, bar);

    // layer 1
    trans_half<<<dim3(G_ / 32, HID_ / 32), dim3(32, 8)>>>(W1, Wrh, HID_, G_);
    zero_state<<<zgrid, 256>>>(h, bar);
    gemm_fp16_pipe<<<MT * (G_ / GBN), 128, GEMM_SMEM>>>(
        HAh, HID_, Wrh, b1, Xg, G_, HID_, G_ / GBN, MT);
    lstm_persist<<<NBLK, 256, SMEM_PERSIST>>>(Xg, W1 + (size_t)HID_ * G_, hh_, HBh, bar);

    // layer 2
    trans_half<<<dim3(G_ / 32, HID_ / 32), dim3(32, 8)>>>(W2, Wrh, HID_, G_);
    zero_state<<<zgrid, 256>>>(h, bar);
    gemm_fp16_pipe<<<MT * (G_ / GBN), 128, GEMM_SMEM>>>(
        HBh, HID_, Wrh, b2, Xg, G_, HID_, G_ / GBN, MT);
    lstm_persist<<<NBLK, 256, SMEM_PERSIST>>>(Xg, W2 + (size_t)HID_ * G_, hh_, HAh, bar);

    // projection: Wd^T (half) into the now-dead Xg buffer, then fp16 GEMM
    trans_half<<<dim3(VOCAB_ / 32, HID_ / 32), dim3(32, 8)>>>(Wd, WdTh, HID_, VOCAB_);
    gemm_fp16_pipe<<<MT * (VOCAB_ / GBN), 128, GEMM_SMEM>>>(
        HAh, HID_, WdTh, bd, out, VOCAB_, HID_, VOCAB_ / GBN, MT);
}